// round 2
// baseline (speedup 1.0000x reference)
#include <cuda_runtime.h>

#define BATCHN 256
#define SEQN   1024
#define HIDN   200
#define VOCABN 33

#define NCPG  50    // colpair-groups (4 cols each): 50*4 = 200 cols
#define NCHK  8     // i-range chunks
#define NI    25    // i per chunk (8*25 = 200)
#define NWRK  (NCPG*NCHK)   // 400 GEMV worker threads
#define NLOG  (2*VOCABN)    // 66 logits threads
#define TPB   480

__device__ float d_E2[VOCABN * HIDN];
__device__ int   d_x_is32;

// ---------------------------------------------------------------------------
// Prep: E2[v][j] = sum_e embedding[v][e] * W_e[e][j]; detect int32 vs int64 x.
// ---------------------------------------------------------------------------
__global__ void prep_kernel(const float* __restrict__ emb,
                            const float* __restrict__ We,
                            const int* __restrict__ x32) {
    int v = blockIdx.x, j = threadIdx.x;
    if (v == 0 && j == 0) {
        int is32 = 0;
        for (int i = 0; i < 128; i++)
            if (x32[2 * i + 1] != 0) is32 = 1;
        d_x_is32 = is32;
    }
    float acc = 0.f;
#pragma unroll 8
    for (int e = 0; e < HIDN; e++)
        acc += emb[v * HIDN + e] * We[e * HIDN + j];
    d_E2[v * HIDN + j] = acc;
}

// ---------------------------------------------------------------------------
struct Smem {
    float4 hdup[HIDN];             // {h0,h0,h1,h1} per column
    float2 hpair[HIDN];            // {h0,h1} per column
    float  e2[VOCABN * HIDN];      // input-projection lookup table
    float4 wodup[VOCABN * 100];    // W_o^T duplicated: [v][p] = {w2p,w2p,w2p+1,w2p+1}
    float4 part[NCHK][2][NCPG];    // GEMV partials: {c0,c1,c2,c3} per group/row
    float2 lp[2][VOCABN];          // logits partials per i-half: {row0,row1}
    int    xi[2][SEQN];            // token ids
};

union F2U { unsigned long long u; float2 f2; };

__device__ __forceinline__ void fma2(unsigned long long& d,
                                     unsigned long long a,
                                     unsigned long long b) {
    asm("fma.rn.f32x2 %0, %1, %2, %0;" : "+l"(d) : "l"(a), "l"(b));
}

__device__ __forceinline__ float fast_tanh(float x) {
    // tanh(x) = 1 - 2/(exp(2x)+1); EX2+RCP based, saturates correctly at +-inf.
    float e = __expf(2.0f * x);
    return 1.0f - __fdividef(2.0f, e + 1.0f);
}

extern __shared__ unsigned char smem_raw[];

__global__ void __launch_bounds__(TPB, 1)
scan_kernel(const void* __restrict__ xv,
            const float* __restrict__ hidden,
            const float* __restrict__ Wh,
            const float* __restrict__ Wo,
            float* __restrict__ out_logits,
            float* __restrict__ out_hidden,
            int write_h) {
    Smem& s = *reinterpret_cast<Smem*>(smem_raw);
    const int tid = threadIdx.x;
    const int b0  = blockIdx.x * 2;

    // ---- setup: tables ----
    for (int k = tid; k < VOCABN * HIDN; k += TPB) s.e2[k] = d_E2[k];
    for (int k = tid; k < VOCABN * 100; k += TPB) {
        int v = k / 100, p = k % 100;
        float w0 = Wo[(2 * p) * VOCABN + v];
        float w1 = Wo[(2 * p + 1) * VOCABN + v];
        s.wodup[k] = make_float4(w0, w0, w1, w1);
    }
    {
        const int is32 = d_x_is32;
        const int* __restrict__ x32 = (const int*)xv;
        const long long* __restrict__ x64 = (const long long*)xv;
        for (int k = tid; k < 2 * SEQN; k += TPB) {
            int r = k >> 10, t = k & (SEQN - 1);
            long long idx = is32 ? (long long)x32[(size_t)(b0 + r) * SEQN + t]
                                 : x64[(size_t)(b0 + r) * SEQN + t];
            s.xi[r][t] = (int)idx;
        }
    }
    for (int j = tid; j < HIDN; j += TPB) {
        float a = hidden[(size_t)b0 * HIDN + j];
        float b = hidden[(size_t)(b0 + 1) * HIDN + j];
        s.hdup[j]  = make_float4(a, a, b, b);
        s.hpair[j] = make_float2(a, b);
    }

    // ---- W_h slice into registers: 4 cols x 25 rows per worker ----
    const int cpg = tid % NCPG;           // cols 4*cpg .. 4*cpg+3
    const int ch  = tid / NCPG;           // i-chunk 0..7
    const int i0  = ch * NI;
    unsigned long long w0r[NI], w1r[NI];
    if (tid < NWRK) {
        const float* wp = Wh + (size_t)i0 * HIDN + 4 * cpg;
#pragma unroll
        for (int ii = 0; ii < NI; ii++) {
            w0r[ii] = *reinterpret_cast<const unsigned long long*>(wp + (size_t)ii * HIDN);
            w1r[ii] = *reinterpret_cast<const unsigned long long*>(wp + (size_t)ii * HIDN + 2);
        }
    }

    // logits mapping (threads NWRK..NWRK+65): (vocab, i-half)
    const int lk = tid - NWRK;
    const int lv = lk % VOCABN;
    const int lh = lk / VOCABN;
    // finalize mapping (threads 0..399): (col, row)
    const int fc = tid % HIDN;
    const int fr = tid / HIDN;

    __syncthreads();

    // ---- main scan ----
    for (int t = 0; t <= SEQN; t++) {
        // Phase 1a: recurrent GEMV partials (4 FFMA2 per LDS.128)
        if (tid < NWRK && t < SEQN) {
            F2U a00, a01, a10, a11;
            a00.u = a01.u = a10.u = a11.u = 0ull;
            const float4* hp = &s.hdup[i0];
#pragma unroll
            for (int ii = 0; ii < NI; ii++) {
                ulonglong2 hd = *reinterpret_cast<const ulonglong2*>(hp + ii);
                fma2(a00.u, w0r[ii], hd.x);
                fma2(a01.u, w1r[ii], hd.x);
                fma2(a10.u, w0r[ii], hd.y);
                fma2(a11.u, w1r[ii], hd.y);
            }
            s.part[ch][0][cpg] = make_float4(a00.f2.x, a00.f2.y, a01.f2.x, a01.f2.y);
            s.part[ch][1][cpg] = make_float4(a10.f2.x, a10.f2.y, a11.f2.x, a11.f2.y);
        }
        // Phase 1b: logits partials for step t-1 (packed rows, LDS.128 operands)
        if (tid >= NWRK && tid < NWRK + NLOG && t > 0) {
            const ulonglong2* wop = reinterpret_cast<const ulonglong2*>(
                &s.wodup[lv * 100 + lh * 50]);
            const ulonglong2* hpp = reinterpret_cast<const ulonglong2*>(
                &s.hpair[lh * 100]);
            F2U l0, l1;
            l0.u = l1.u = 0ull;
#pragma unroll
            for (int ii = 0; ii < 50; ii++) {
                ulonglong2 w4 = wop[ii];
                ulonglong2 h4 = hpp[ii];
                fma2(l0.u, w4.x, h4.x);
                fma2(l1.u, w4.y, h4.y);
            }
            s.lp[lh][lv] = make_float2(l0.f2.x + l1.f2.x, l0.f2.y + l1.f2.y);
        }
        __syncthreads();

        // Phase 2a: finalize h_t (400 threads, 1 tanh each)
        if (tid < 2 * HIDN && t < SEQN) {
            float sum = 0.f;
            const float* pb = reinterpret_cast<const float*>(s.part);
#pragma unroll
            for (int c = 0; c < NCHK; c++)
                sum += pb[((c * 2 + fr) * NCPG + (fc >> 2)) * 4 + (fc & 3)];
            const int xi = s.xi[fr][t];
            float h = fast_tanh(sum + s.e2[xi * HIDN + fc]);
            reinterpret_cast<float2*>(&s.hdup[fc])[fr] = make_float2(h, h);
            reinterpret_cast<float*>(&s.hpair[fc])[fr] = h;
        }
        // Phase 2b: store logits for step t-1
        if (tid >= NWRK && tid < NWRK + NLOG && t > 0) {
            float lg = reinterpret_cast<const float*>(&s.lp[0][lv])[lh]
                     + reinterpret_cast<const float*>(&s.lp[1][lv])[lh];
            out_logits[(size_t)(b0 + lh) * SEQN * VOCABN
                       + (size_t)(t - 1) * VOCABN + lv] = lg;
        }
        __syncthreads();
    }

    // ---- final hidden ----
    if (write_h && tid < 2 * HIDN)
        out_hidden[(size_t)(b0 + fr) * HIDN + fc] =
            reinterpret_cast<const float*>(&s.hpair[fc])[fr];
}

// ---------------------------------------------------------------------------
extern "C" void kernel_launch(void* const* d_in, const int* in_sizes, int n_in,
                              void* d_out, int out_size) {
    const void*  x      = d_in[0];
    const float* hidden = (const float*)d_in[1];
    const float* emb    = (const float*)d_in[2];
    const float* We     = (const float*)d_in[3];
    const float* Wh     = (const float*)d_in[4];
    const float* Wo     = (const float*)d_in[5];

    float* logits = (float*)d_out;
    const long long LOGITS_ELEMS = (long long)BATCHN * SEQN * VOCABN;
    int write_h = (out_size >= (int)(LOGITS_ELEMS + BATCHN * HIDN));
    float* outh = logits + LOGITS_ELEMS;

    prep_kernel<<<VOCABN, HIDN>>>(emb, We, (const int*)x);

    cudaFuncSetAttribute((const void*)scan_kernel,
                         cudaFuncAttributeMaxDynamicSharedMemorySize,
                         (int)sizeof(Smem));
    scan_kernel<<<BATCHN / 2, TPB, sizeof(Smem)>>>(
        x, hidden, Wh, Wo, logits, outh, write_h);
}

// round 3
// speedup vs baseline: 1.0130x; 1.0130x over previous
#include <cuda_runtime.h>

#define BATCHN 256
#define SEQN   1024
#define HIDN   200
#define VOCABN 33

#define NCPG  50            // col-groups of 4 cols: 50*4 = 200
#define NCHK  10            // i-chunks
#define NI    20            // i per chunk (10*20 = 200)
#define NWRK  (NCPG*NCHK)   // 500 GEMV workers
#define NLOG  (2*VOCABN)    // 66 logits threads
#define TPB   576           // 18 warps; reg cap 112
#define WOTP  204           // padded wot row (51 x 16B, odd -> conflict-free)

__device__ float d_E2[VOCABN * HIDN];
__device__ int   d_x_is32;

// ---------------------------------------------------------------------------
__global__ void prep_kernel(const float* __restrict__ emb,
                            const float* __restrict__ We,
                            const int* __restrict__ x32) {
    int v = blockIdx.x, j = threadIdx.x;
    if (v == 0 && j == 0) {
        int is32 = 0;
        for (int i = 0; i < 128; i++)
            if (x32[2 * i + 1] != 0) is32 = 1;
        d_x_is32 = is32;
    }
    float acc = 0.f;
#pragma unroll 8
    for (int e = 0; e < HIDN; e++)
        acc += emb[v * HIDN + e] * We[e * HIDN + j];
    d_E2[v * HIDN + j] = acc;
}

// ---------------------------------------------------------------------------
struct __align__(16) Smem {
    float4 hdup[HIDN];               // {h_r0,h_r0,h_r1,h_r1} per column
    float4 part[NCHK][2][NCPG];      // GEMV partials {c0,c1,c2,c3}
    float  hrow[2][2][HIDN];         // [parity][row][col]
    float  e2[VOCABN * HIDN];        // input-projection table
    float  wot[VOCABN][WOTP];        // W_o transposed [v][i], padded
    int    xi[2][SEQN];              // token ids
};

union F2U { unsigned long long u; float2 f2; };

__device__ __forceinline__ void fma2(unsigned long long& d,
                                     unsigned long long a,
                                     unsigned long long b) {
    asm("fma.rn.f32x2 %0, %1, %2, %0;" : "+l"(d) : "l"(a), "l"(b));
}

__device__ __forceinline__ float fast_tanh(float x) {
    float e = __expf(2.0f * x);
    return 1.0f - __fdividef(2.0f, e + 1.0f);
}

extern __shared__ unsigned char smem_raw[];

__global__ void __launch_bounds__(TPB, 1)
scan_kernel(const void* __restrict__ xv,
            const float* __restrict__ hidden,
            const float* __restrict__ Wh,
            const float* __restrict__ Wo,
            float* __restrict__ out_logits,
            float* __restrict__ out_hidden,
            int write_h) {
    Smem& s = *reinterpret_cast<Smem*>(smem_raw);
    const int tid = threadIdx.x;
    const int b0  = blockIdx.x * 2;

    // ---- setup ----
    for (int k = tid; k < VOCABN * HIDN; k += TPB) s.e2[k] = d_E2[k];
    for (int k = tid; k < VOCABN * HIDN; k += TPB) {
        int v = k / HIDN, i = k % HIDN;
        s.wot[v][i] = Wo[i * VOCABN + v];
    }
    {
        const int is32 = d_x_is32;
        const int* __restrict__ x32 = (const int*)xv;
        const long long* __restrict__ x64 = (const long long*)xv;
        for (int k = tid; k < 2 * SEQN; k += TPB) {
            int r = k >> 10, t = k & (SEQN - 1);
            long long idx = is32 ? (long long)x32[(size_t)(b0 + r) * SEQN + t]
                                 : x64[(size_t)(b0 + r) * SEQN + t];
            s.xi[r][t] = (int)idx;
        }
    }
    for (int j = tid; j < HIDN; j += TPB) {
        float a = hidden[(size_t)b0 * HIDN + j];
        float b = hidden[(size_t)(b0 + 1) * HIDN + j];
        s.hdup[j] = make_float4(a, a, b, b);
    }

    // ---- worker W_h slice: 4 cols x 20 rows -> 80 regs ----
    const int cpg = tid % NCPG;          // cols 4*cpg..4*cpg+3
    const int ch  = tid / NCPG;          // 0..9 (>=10 -> non-worker)
    const int i0  = ch * NI;
    unsigned long long w0r[NI], w1r[NI];
    if (tid < NWRK) {
        const float* wp = Wh + (size_t)i0 * HIDN + 4 * cpg;
#pragma unroll
        for (int ii = 0; ii < NI; ii++) {
            w0r[ii] = *reinterpret_cast<const unsigned long long*>(wp + (size_t)ii * HIDN);
            w1r[ii] = *reinterpret_cast<const unsigned long long*>(wp + (size_t)ii * HIDN + 2);
        }
    }

    // logits mapping: tids 500..565 -> (lv, lrow)
    const int lk   = tid - NWRK;
    const int lv   = (lk >= 0 && lk < NLOG) ? lk % VOCABN : 0;
    const int lrow = (lk >= 0 && lk < NLOG) ? lk / VOCABN : 0;
    const bool is_log = (lk >= 0 && lk < NLOG);
    // finalize mapping: tids 0..399 -> (fc, fr)
    const int fc = tid % HIDN;
    const int fr = tid / HIDN;

    __syncthreads();

    F2U lacc0, lacc1;

    for (int t = 0; t <= SEQN; t++) {
        // ---- Phase 1 ----
        if (tid < NWRK && t < SEQN) {
            F2U a00, a01, a10, a11;
            a00.u = a01.u = a10.u = a11.u = 0ull;
            const float4* hp = &s.hdup[i0];
#pragma unroll
            for (int ii = 0; ii < NI; ii++) {
                ulonglong2 hd = *reinterpret_cast<const ulonglong2*>(hp + ii);
                fma2(a00.u, w0r[ii], hd.x);
                fma2(a01.u, w1r[ii], hd.x);
                fma2(a10.u, w0r[ii], hd.y);
                fma2(a11.u, w1r[ii], hd.y);
            }
            s.part[ch][0][cpg] = make_float4(a00.f2.x, a00.f2.y, a01.f2.x, a01.f2.y);
            s.part[ch][1][cpg] = make_float4(a10.f2.x, a10.f2.y, a11.f2.x, a11.f2.y);
        } else if (is_log && t > 0) {
            // logits first half: i = 0..99, using h_{t-1} in hrow[(t-1)&1]
            lacc0.u = lacc1.u = 0ull;
            const float4* wp4 = reinterpret_cast<const float4*>(&s.wot[lv][0]);
            const ulonglong2* hp4 = reinterpret_cast<const ulonglong2*>(
                &s.hrow[(t - 1) & 1][lrow][0]);
#pragma unroll
            for (int q = 0; q < 25; q++) {
                float4 w4 = wp4[q];
                ulonglong2 h4 = hp4[q];
                F2U w01, w23;
                w01.f2 = make_float2(w4.x, w4.y);
                w23.f2 = make_float2(w4.z, w4.w);
                fma2(lacc0.u, h4.x, w01.u);
                fma2(lacc1.u, h4.y, w23.u);
            }
        }
        __syncthreads();

        // ---- Phase 2 ----
        if (tid < 2 * HIDN && t < SEQN) {
            float sum = 0.f;
#pragma unroll
            for (int c = 0; c < NCHK; c++)
                sum += reinterpret_cast<const float*>(&s.part[c][fr][fc >> 2])[fc & 3];
            const int xi = s.xi[fr][t];
            float h = fast_tanh(sum + s.e2[xi * HIDN + fc]);
            reinterpret_cast<float2*>(&s.hdup[fc])[fr] = make_float2(h, h);
            s.hrow[t & 1][fr][fc] = h;
        } else if (is_log && t > 0) {
            // logits second half: i = 100..199, then store for step t-1
            const float4* wp4 = reinterpret_cast<const float4*>(&s.wot[lv][100]);
            const ulonglong2* hp4 = reinterpret_cast<const ulonglong2*>(
                &s.hrow[(t - 1) & 1][lrow][100]);
#pragma unroll
            for (int q = 0; q < 25; q++) {
                float4 w4 = wp4[q];
                ulonglong2 h4 = hp4[q];
                F2U w01, w23;
                w01.f2 = make_float2(w4.x, w4.y);
                w23.f2 = make_float2(w4.z, w4.w);
                fma2(lacc0.u, h4.x, w01.u);
                fma2(lacc1.u, h4.y, w23.u);
            }
            out_logits[(size_t)(b0 + lrow) * SEQN * VOCABN
                       + (size_t)(t - 1) * VOCABN + lv] =
                (lacc0.f2.x + lacc0.f2.y) + (lacc1.f2.x + lacc1.f2.y);
        }
        __syncthreads();
    }

    // ---- final hidden: h_{SEQ-1} lives in hrow[(SEQN-1)&1] ----
    if (write_h && tid < 2 * HIDN)
        out_hidden[(size_t)(b0 + fr) * HIDN + fc] = s.hrow[(SEQN - 1) & 1][fr][fc];
}

// ---------------------------------------------------------------------------
extern "C" void kernel_launch(void* const* d_in, const int* in_sizes, int n_in,
                              void* d_out, int out_size) {
    const void*  x      = d_in[0];
    const float* hidden = (const float*)d_in[1];
    const float* emb    = (const float*)d_in[2];
    const float* We     = (const float*)d_in[3];
    const float* Wh     = (const float*)d_in[4];
    const float* Wo     = (const float*)d_in[5];

    float* logits = (float*)d_out;
    const long long LOGITS_ELEMS = (long long)BATCHN * SEQN * VOCABN;
    int write_h = (out_size >= (int)(LOGITS_ELEMS + BATCHN * HIDN));
    float* outh = logits + LOGITS_ELEMS;

    prep_kernel<<<VOCABN, HIDN>>>(emb, We, (const int*)x);

    cudaFuncSetAttribute((const void*)scan_kernel,
                         cudaFuncAttributeMaxDynamicSharedMemorySize,
                         (int)sizeof(Smem));
    scan_kernel<<<BATCHN / 2, TPB, sizeof(Smem)>>>(
        x, hidden, Wh, Wo, logits, outh, write_h);
}